// round 5
// baseline (speedup 1.0000x reference)
#include <cuda_runtime.h>
#include <cuda_bf16.h>
#include <stdint.h>

// cdist: out[i,j] = sqrt(max(||xi||^2 + ||xj||^2 - 2*dot(xi,xj), 0))
// dot via bf16 hi/lo split on mma.sync: dot ~= hiA.hiB + hiA.loB + loA.hiB.
// R5: one-time prep kernel (bf16 split + swizzle + B-row-permute + norms),
// persistent CTAs with contiguous tile chunks, cp.async tile loads,
// A-tile reuse across a row, double-buffered B prefetch.

#define NPTS   16384
#define NT_X   (NPTS / 128)
#define NTILES (NT_X * NT_X)
#define GRID_CTAS 296          // 148 SMs x 2 resident CTAs

// prepped row: 128 bytes = 64 bf16 (hi cols 0..31 | lo cols 32..63),
// stored as 8x16B chunks, chunk c placed at index (c ^ (row & 7)).
__device__ __align__(128) uint8_t Aprep[(size_t)NPTS * 128];
__device__ __align__(128) uint8_t Bprep[(size_t)NPTS * 128];
__device__ float sqg[NPTS];

__device__ __forceinline__ float sqrt_approx(float v) {
    float r; asm("sqrt.approx.f32 %0, %1;" : "=f"(r) : "f"(v)); return r;
}
__device__ __forceinline__ float dist_val(float si, float sj, float dot) {
    return sqrt_approx(fmaxf(fmaf(-2.0f, dot, si + sj), 0.0f));
}
__device__ __forceinline__ uint32_t smem_u32(const void* p) {
    return (uint32_t)__cvta_generic_to_shared(p);
}
__device__ __forceinline__ void ldmatrix_x4(uint32_t* r, uint32_t addr) {
    asm volatile("ldmatrix.sync.aligned.m8n8.x4.shared.b16 {%0,%1,%2,%3}, [%4];"
                 : "=r"(r[0]), "=r"(r[1]), "=r"(r[2]), "=r"(r[3]) : "r"(addr));
}
__device__ __forceinline__ void mma_bf16(float* c, const uint32_t* a, const uint32_t* b) {
    asm volatile(
        "mma.sync.aligned.m16n8k16.row.col.f32.bf16.bf16.f32 "
        "{%0,%1,%2,%3}, {%4,%5,%6,%7}, {%8,%9}, {%0,%1,%2,%3};"
        : "+f"(c[0]), "+f"(c[1]), "+f"(c[2]), "+f"(c[3])
        : "r"(a[0]), "r"(a[1]), "r"(a[2]), "r"(a[3]), "r"(b[0]), "r"(b[1]));
}
__device__ __forceinline__ void cp16(uint32_t s, const void* g) {
    asm volatile("cp.async.cg.shared.global [%0], [%1], 16;"
                 :: "r"(s), "l"(g) : "memory");
}
#define CP_COMMIT() asm volatile("cp.async.commit_group;" ::: "memory")
#define CP_WAIT0()  asm volatile("cp.async.wait_group 0;" ::: "memory")

// ---------------- prep kernel: one thread per row ----------------
__global__ void __launch_bounds__(256)
prep_kernel(const float* __restrict__ x)
{
    const int g = blockIdx.x * blockDim.x + threadIdx.x;   // row 0..16383
    const float4* xr = (const float4*)(x + ((size_t)g << 5));
    uint32_t Hw[16], Lw[16];
    float s = 0.0f;
#pragma unroll
    for (int q = 0; q < 8; q++) {
        float4 v = xr[q];
        s = fmaf(v.x, v.x, s); s = fmaf(v.y, v.y, s);
        s = fmaf(v.z, v.z, s); s = fmaf(v.w, v.w, s);
        __nv_bfloat16 hx = __float2bfloat16_rn(v.x);
        __nv_bfloat16 hy = __float2bfloat16_rn(v.y);
        __nv_bfloat16 hz = __float2bfloat16_rn(v.z);
        __nv_bfloat16 hw = __float2bfloat16_rn(v.w);
        __nv_bfloat162 h01 = __halves2bfloat162(hx, hy);
        __nv_bfloat162 h23 = __halves2bfloat162(hz, hw);
        __nv_bfloat162 l01 = __floats2bfloat162_rn(v.x - __bfloat162float(hx),
                                                   v.y - __bfloat162float(hy));
        __nv_bfloat162 l23 = __floats2bfloat162_rn(v.z - __bfloat162float(hz),
                                                   v.w - __bfloat162float(hw));
        Hw[2 * q + 0] = *(uint32_t*)&h01; Hw[2 * q + 1] = *(uint32_t*)&h23;
        Lw[2 * q + 0] = *(uint32_t*)&l01; Lw[2 * q + 1] = *(uint32_t*)&l23;
    }
    sqg[g] = s;

    uint4 ch[8];   // chunks: 0..3 = hi (bf16 cols 0..31), 4..7 = lo
#pragma unroll
    for (int c = 0; c < 4; c++) {
        ch[c]     = make_uint4(Hw[4 * c], Hw[4 * c + 1], Hw[4 * c + 2], Hw[4 * c + 3]);
        ch[c + 4] = make_uint4(Lw[4 * c], Lw[4 * c + 1], Lw[4 * c + 2], Lw[4 * c + 3]);
    }

    uint4* Arow = (uint4*)(Aprep + (size_t)g * 128);
    const int ra = g & 7;
#pragma unroll
    for (int c = 0; c < 8; c++) Arow[c ^ ra] = ch[c];

    // B: row-permuted within each 16-group (epilogue STG.128 permutation)
    const int v = g & 15, w = v >> 1, r = v & 1;
    const int p = (g & ~15) | ((w & 1) << 3) | ((w >> 1) << 1) | r;
    uint4* Brow = (uint4*)(Bprep + (size_t)p * 128);
    const int rb = p & 7;
#pragma unroll
    for (int c = 0; c < 8; c++) Brow[c ^ rb] = ch[c];
}

// ---------------- main kernel ----------------
// dynamic smem layout
#define SM_A    0
#define SM_B0   16384
#define SM_B1   32768
#define SM_SQA  49152
#define SM_SQB0 49664
#define SM_SQB1 50176
#define SM_TOTAL 50688

__device__ __forceinline__ void load_tile(uint32_t sdst, const uint8_t* gsrc, int t) {
    const uint8_t* g = gsrc + t * 64;
    const uint32_t s = sdst + (uint32_t)t * 64;
#pragma unroll
    for (int i = 0; i < 4; i++) cp16(s + i * 16, g + i * 16);
}
__device__ __forceinline__ void load_sq(uint32_t sdst, const float* gsrc, int t) {
    if (t < 32) cp16(sdst + (uint32_t)t * 16, gsrc + t * 4);
}

__global__ void __launch_bounds__(256, 2)
cdist_main(float* __restrict__ out)
{
    extern __shared__ __align__(128) uint8_t smem[];
    const uint32_t sb = smem_u32(smem);
    const int t    = threadIdx.x;
    const int lane = t & 31;
    const int wid  = t >> 5;

    const int per = (NTILES + (int)gridDim.x - 1) / (int)gridDim.x;
    const int tbeg = blockIdx.x * per;
    const int tend = min(tbeg + per, NTILES);
    if (tbeg >= tend) return;

    const int wr = wid >> 2;
    const int wc = wid & 3;
    const uint32_t xmask  = (uint32_t)(lane & 7) << 4;
    const uint32_t aKhalf = (uint32_t)(lane >> 4) << 4;
    const uint32_t bKhalf = (uint32_t)((lane >> 3) & 1) << 4;
    const uint32_t aBase0 = sb + SM_A + (uint32_t)(wr * 64 + (lane & 15)) * 128;
    const uint32_t bRowOff = (uint32_t)(wc * 32 + ((lane >> 4) << 3) + (lane & 7)) * 128;

    int cur = 0;
    int a0 = (tbeg >> 7) << 7;
    // prologue loads
    load_tile(sb + SM_A,  Aprep + (size_t)a0 * 128, t);
    load_tile(sb + SM_B0, Bprep + (size_t)((tbeg & 127) << 7) * 128, t);
    load_sq(sb + SM_SQA,  sqg + a0, t);
    load_sq(sb + SM_SQB0, sqg + ((tbeg & 127) << 7), t);
    CP_COMMIT(); CP_WAIT0(); __syncthreads();

    for (int tt = tbeg; tt < tend; ++tt) {
        const int b0 = (tt & 127) << 7;
        const int nt = tt + 1;
        const int na0 = (nt >> 7) << 7;
        const bool more = (nt < tend);
        const bool pf = more && (na0 == a0);
        if (pf) {  // prefetch next B while computing
            const int nb0 = (nt & 127) << 7;
            load_tile(sb + (cur ? SM_B0 : SM_B1), Bprep + (size_t)nb0 * 128, t);
            load_sq(sb + (cur ? SM_SQB0 : SM_SQB1), sqg + nb0, t);
            CP_COMMIT();
        }

        // ---- warp GEMM 64x32, hi/lo fused ----
        const uint32_t bBase = sb + (cur ? SM_B1 : SM_B0) + bRowOff;
        float acc[4][4][4];
#pragma unroll
        for (int mt = 0; mt < 4; mt++)
#pragma unroll
            for (int ntl = 0; ntl < 4; ntl++)
#pragma unroll
                for (int i = 0; i < 4; i++) acc[mt][ntl][i] = 0.0f;

#pragma unroll
        for (int ks = 0; ks < 2; ks++) {
            const uint32_t ahOff = (uint32_t)(ks * 32) + aKhalf;
            const uint32_t bhOff = (uint32_t)(ks * 32) + bKhalf;
            uint32_t ah[4][4], al[4][4], bh[2][4], bl[2][4];
#pragma unroll
            for (int mt = 0; mt < 4; mt++)
                ldmatrix_x4(ah[mt], aBase0 + (uint32_t)mt * 2048 + (ahOff ^ xmask));
#pragma unroll
            for (int u = 0; u < 2; u++)
                ldmatrix_x4(bh[u], bBase + (uint32_t)u * 2048 + (bhOff ^ xmask));
#pragma unroll
            for (int mt = 0; mt < 4; mt++)
#pragma unroll
                for (int ntl = 0; ntl < 4; ntl++)
                    mma_bf16(acc[mt][ntl], ah[mt], &bh[ntl >> 1][(ntl & 1) * 2]);
#pragma unroll
            for (int u = 0; u < 2; u++)
                ldmatrix_x4(bl[u], bBase + (uint32_t)u * 2048 + ((bhOff + 64) ^ xmask));
#pragma unroll
            for (int mt = 0; mt < 4; mt++)
#pragma unroll
                for (int ntl = 0; ntl < 4; ntl++)
                    mma_bf16(acc[mt][ntl], ah[mt], &bl[ntl >> 1][(ntl & 1) * 2]);
#pragma unroll
            for (int mt = 0; mt < 4; mt++)
                ldmatrix_x4(al[mt], aBase0 + (uint32_t)mt * 2048 + ((ahOff + 64) ^ xmask));
#pragma unroll
            for (int mt = 0; mt < 4; mt++)
#pragma unroll
                for (int ntl = 0; ntl < 4; ntl++)
                    mma_bf16(acc[mt][ntl], al[mt], &bh[ntl >> 1][(ntl & 1) * 2]);
        }

        // ---- epilogue: STG.128 ----
        const float* sqa = (const float*)(smem + SM_SQA);
        const float* sqb = (const float*)(smem + (cur ? SM_SQB1 : SM_SQB0));
        const int q  = lane & 3;
        const int gr = lane >> 2;
        const bool diag = (a0 == b0);
#pragma unroll
        for (int mt = 0; mt < 4; mt++) {
            const int r0l = wr * 64 + mt * 16 + gr;
            const int r1l = r0l + 8;
            const float si0 = sqa[r0l], si1 = sqa[r1l];
            const int g0 = a0 + r0l, g1 = a0 + r1l;
            float* __restrict__ o0 = out + ((size_t)g0 << 14);
            float* __restrict__ o1 = out + ((size_t)g1 << 14);
#pragma unroll
            for (int u = 0; u < 2; u++) {
                const int cl = wc * 32 + u * 16 + q * 4;
                const int gc = b0 + cl;
                const float4 sj = *(const float4*)&sqb[cl];
                const float* p0 = acc[mt][2 * u];
                const float* p1 = acc[mt][2 * u + 1];
                float4 w0, w1;
                w0.x = dist_val(si0, sj.x, p0[0]);
                w0.y = dist_val(si0, sj.y, p0[1]);
                w0.z = dist_val(si0, sj.z, p1[0]);
                w0.w = dist_val(si0, sj.w, p1[1]);
                w1.x = dist_val(si1, sj.x, p0[2]);
                w1.y = dist_val(si1, sj.y, p0[3]);
                w1.z = dist_val(si1, sj.z, p1[2]);
                w1.w = dist_val(si1, sj.w, p1[3]);
                if (diag) {
                    const int d0 = g0 - gc;
                    if (d0 >= 0 && d0 < 4) ((float*)&w0)[d0] = 0.0f;
                    const int d1 = g1 - gc;
                    if (d1 >= 0 && d1 < 4) ((float*)&w1)[d1] = 0.0f;
                }
                *(float4*)(o0 + gc) = w0;
                *(float4*)(o1 + gc) = w1;
            }
        }

        if (more) {
            __syncthreads();   // all reads of current buffers complete
            if (!pf) {         // row changed: reload A (+ B into other buffer)
                const int nb0 = (nt & 127) << 7;
                load_tile(sb + SM_A, Aprep + (size_t)na0 * 128, t);
                load_sq(sb + SM_SQA, sqg + na0, t);
                load_tile(sb + (cur ? SM_B0 : SM_B1), Bprep + (size_t)nb0 * 128, t);
                load_sq(sb + (cur ? SM_SQB0 : SM_SQB1), sqg + nb0, t);
                CP_COMMIT();
                a0 = na0;
            }
            CP_WAIT0();
            __syncthreads();
            cur ^= 1;
        }
    }
}

extern "C" void kernel_launch(void* const* d_in, const int* in_sizes, int n_in,
                              void* d_out, int out_size)
{
    (void)in_sizes; (void)n_in; (void)out_size;
    const float* x = (const float*)d_in[0];
    float* out = (float*)d_out;
    prep_kernel<<<NPTS / 256, 256>>>(x);
    cudaFuncSetAttribute(cdist_main,
                         cudaFuncAttributeMaxDynamicSharedMemorySize, SM_TOTAL);
    cdist_main<<<GRID_CTAS, 256, SM_TOTAL>>>(out);
}

// round 6
// speedup vs baseline: 1.1332x; 1.1332x over previous
#include <cuda_runtime.h>
#include <cuda_bf16.h>
#include <stdint.h>

// cdist: out[i,j] = sqrt(max(||xi||^2 + ||xj||^2 - 2*dot(xi,xj), 0))
// dot via bf16 hi/lo split on mma.sync: dot ~= hiA.hiB + hiA.loB + loA.hiB.
// R6: R4's one-tile-per-CTA structure (grid-level overlap) + R5's prep kernel
// (bf16 hi/lo split, SW128 chunk layout, B-row permutation, norms) so the
// main kernel does zero conversion math; tiles come in via cp.async.

#define NPTS   16384

// prepped row: 128 bytes = 64 bf16 (hi cols 0..31 | lo cols 32..63),
// stored as 8x16B chunks, chunk c placed at index (c ^ (row & 7)).
__device__ __align__(128) uint8_t Aprep[(size_t)NPTS * 128];
__device__ __align__(128) uint8_t Bprep[(size_t)NPTS * 128];
__device__ float sqg[NPTS];

__device__ __forceinline__ float sqrt_approx(float v) {
    float r; asm("sqrt.approx.f32 %0, %1;" : "=f"(r) : "f"(v)); return r;
}
__device__ __forceinline__ float dist_val(float si, float sj, float dot) {
    return sqrt_approx(fmaxf(fmaf(-2.0f, dot, si + sj), 0.0f));
}
__device__ __forceinline__ uint32_t smem_u32(const void* p) {
    return (uint32_t)__cvta_generic_to_shared(p);
}
__device__ __forceinline__ void ldmatrix_x4(uint32_t* r, uint32_t addr) {
    asm volatile("ldmatrix.sync.aligned.m8n8.x4.shared.b16 {%0,%1,%2,%3}, [%4];"
                 : "=r"(r[0]), "=r"(r[1]), "=r"(r[2]), "=r"(r[3]) : "r"(addr));
}
__device__ __forceinline__ void mma_bf16(float* c, const uint32_t* a, const uint32_t* b) {
    asm volatile(
        "mma.sync.aligned.m16n8k16.row.col.f32.bf16.bf16.f32 "
        "{%0,%1,%2,%3}, {%4,%5,%6,%7}, {%8,%9}, {%0,%1,%2,%3};"
        : "+f"(c[0]), "+f"(c[1]), "+f"(c[2]), "+f"(c[3])
        : "r"(a[0]), "r"(a[1]), "r"(a[2]), "r"(a[3]), "r"(b[0]), "r"(b[1]));
}
__device__ __forceinline__ void cp16(uint32_t s, const void* g) {
    asm volatile("cp.async.cg.shared.global [%0], [%1], 16;"
                 :: "r"(s), "l"(g) : "memory");
}
#define CP_COMMIT() asm volatile("cp.async.commit_group;" ::: "memory")
#define CP_WAIT0()  asm volatile("cp.async.wait_group 0;" ::: "memory")

// ---------------- prep kernel: one thread per row ----------------
__global__ void __launch_bounds__(256)
prep_kernel(const float* __restrict__ x)
{
    const int g = blockIdx.x * blockDim.x + threadIdx.x;   // row 0..16383
    const float4* xr = (const float4*)(x + ((size_t)g << 5));
    uint32_t Hw[16], Lw[16];
    float s = 0.0f;
#pragma unroll
    for (int q = 0; q < 8; q++) {
        float4 v = xr[q];
        s = fmaf(v.x, v.x, s); s = fmaf(v.y, v.y, s);
        s = fmaf(v.z, v.z, s); s = fmaf(v.w, v.w, s);
        __nv_bfloat16 hx = __float2bfloat16_rn(v.x);
        __nv_bfloat16 hy = __float2bfloat16_rn(v.y);
        __nv_bfloat16 hz = __float2bfloat16_rn(v.z);
        __nv_bfloat16 hw = __float2bfloat16_rn(v.w);
        __nv_bfloat162 h01 = __halves2bfloat162(hx, hy);
        __nv_bfloat162 h23 = __halves2bfloat162(hz, hw);
        __nv_bfloat162 l01 = __floats2bfloat162_rn(v.x - __bfloat162float(hx),
                                                   v.y - __bfloat162float(hy));
        __nv_bfloat162 l23 = __floats2bfloat162_rn(v.z - __bfloat162float(hz),
                                                   v.w - __bfloat162float(hw));
        Hw[2 * q + 0] = *(uint32_t*)&h01; Hw[2 * q + 1] = *(uint32_t*)&h23;
        Lw[2 * q + 0] = *(uint32_t*)&l01; Lw[2 * q + 1] = *(uint32_t*)&l23;
    }
    sqg[g] = s;

    uint4 ch[8];   // chunks: 0..3 = hi (bf16 cols 0..31), 4..7 = lo
#pragma unroll
    for (int c = 0; c < 4; c++) {
        ch[c]     = make_uint4(Hw[4 * c], Hw[4 * c + 1], Hw[4 * c + 2], Hw[4 * c + 3]);
        ch[c + 4] = make_uint4(Lw[4 * c], Lw[4 * c + 1], Lw[4 * c + 2], Lw[4 * c + 3]);
    }

    uint4* Arow = (uint4*)(Aprep + (size_t)g * 128);
    const int ra = g & 7;
#pragma unroll
    for (int c = 0; c < 8; c++) Arow[c ^ ra] = ch[c];

    // B: row-permuted within each 16-group (epilogue STG.128 permutation)
    const int v = g & 15, w = v >> 1, r = v & 1;
    const int p = (g & ~15) | ((w & 1) << 3) | ((w >> 1) << 1) | r;
    uint4* Brow = (uint4*)(Bprep + (size_t)p * 128);
    const int rb = p & 7;
#pragma unroll
    for (int c = 0; c < 8; c++) Brow[c ^ rb] = ch[c];
}

// ---------------- main kernel: one 128x128 tile per CTA ----------------
__global__ void __launch_bounds__(256, 2)
cdist_mma_kernel(float* __restrict__ out)
{
    __shared__ __align__(128) uint8_t Abuf[128 * 128];
    __shared__ __align__(128) uint8_t Bbuf[128 * 128];
    __shared__ float sqa[128];
    __shared__ float sqb[128];

    const int t    = threadIdx.x;
    const int lane = t & 31;
    const int wid  = t >> 5;
    const int a0   = blockIdx.y << 7;
    const int b0   = blockIdx.x << 7;

    // ---- async tile loads from prepped image (64B per thread per side) ----
    {
        const uint32_t sA = smem_u32(Abuf) + (uint32_t)t * 64;
        const uint32_t sB = smem_u32(Bbuf) + (uint32_t)t * 64;
        const uint8_t* gA = Aprep + (size_t)a0 * 128 + (size_t)t * 64;
        const uint8_t* gB = Bprep + (size_t)b0 * 128 + (size_t)t * 64;
#pragma unroll
        for (int i = 0; i < 4; i++) {
            cp16(sA + i * 16, gA + i * 16);
            cp16(sB + i * 16, gB + i * 16);
        }
        if (t < 32)       cp16(smem_u32(sqa) + (uint32_t)t * 16, sqg + a0 + t * 4);
        else if (t < 64)  cp16(smem_u32(sqb) + (uint32_t)(t - 32) * 16,
                               sqg + b0 + (t - 32) * 4);
        CP_COMMIT();
        CP_WAIT0();
    }
    __syncthreads();

    // ---- warp GEMM: warp tile 64x32, 2x4 warp grid ----
    const int wr = wid >> 2;
    const int wc = wid & 3;
    const uint32_t aBase  = smem_u32(Abuf) + (uint32_t)(wr * 64 + (lane & 15)) * 128;
    const uint32_t aKhalf = (uint32_t)(lane >> 4) << 4;
    const uint32_t xmask  = (uint32_t)(lane & 7) << 4;
    const uint32_t bBase  = smem_u32(Bbuf) +
        (uint32_t)(wc * 32 + ((lane >> 4) << 3) + (lane & 7)) * 128;
    const uint32_t bKhalf = (uint32_t)((lane >> 3) & 1) << 4;

    float acc[4][4][4];
#pragma unroll
    for (int mt = 0; mt < 4; mt++)
#pragma unroll
        for (int nt = 0; nt < 4; nt++)
#pragma unroll
            for (int i = 0; i < 4; i++) acc[mt][nt][i] = 0.0f;

#pragma unroll
    for (int ks = 0; ks < 2; ks++) {
        const uint32_t ahOff = (uint32_t)(ks * 32) + aKhalf;
        const uint32_t bhOff = (uint32_t)(ks * 32) + bKhalf;
        uint32_t ah[4][4], al[4][4], bh[2][4], bl[2][4];

#pragma unroll
        for (int mt = 0; mt < 4; mt++)
            ldmatrix_x4(ah[mt], aBase + (uint32_t)mt * 2048 + (ahOff ^ xmask));
#pragma unroll
        for (int u = 0; u < 2; u++)
            ldmatrix_x4(bh[u], bBase + (uint32_t)u * 2048 + (bhOff ^ xmask));
        // hi . hi
#pragma unroll
        for (int mt = 0; mt < 4; mt++)
#pragma unroll
            for (int nt = 0; nt < 4; nt++)
                mma_bf16(acc[mt][nt], ah[mt], &bh[nt >> 1][(nt & 1) * 2]);

#pragma unroll
        for (int u = 0; u < 2; u++)
            ldmatrix_x4(bl[u], bBase + (uint32_t)u * 2048 + ((bhOff + 64) ^ xmask));
        // hi . lo
#pragma unroll
        for (int mt = 0; mt < 4; mt++)
#pragma unroll
            for (int nt = 0; nt < 4; nt++)
                mma_bf16(acc[mt][nt], ah[mt], &bl[nt >> 1][(nt & 1) * 2]);

#pragma unroll
        for (int mt = 0; mt < 4; mt++)
            ldmatrix_x4(al[mt], aBase + (uint32_t)mt * 2048 + ((ahOff + 64) ^ xmask));
        // lo . hi
#pragma unroll
        for (int mt = 0; mt < 4; mt++)
#pragma unroll
            for (int nt = 0; nt < 4; nt++)
                mma_bf16(acc[mt][nt], al[mt], &bh[nt >> 1][(nt & 1) * 2]);
    }

    // ---- epilogue: STG.128, 4 contiguous global cols per thread ----
    const int q  = lane & 3;
    const int gr = lane >> 2;
    const bool diag = (a0 == b0);
#pragma unroll
    for (int mt = 0; mt < 4; mt++) {
        const int r0l = wr * 64 + mt * 16 + gr;
        const int r1l = r0l + 8;
        const float si0 = sqa[r0l], si1 = sqa[r1l];
        const int g0 = a0 + r0l, g1 = a0 + r1l;
        float* __restrict__ o0 = out + ((size_t)g0 << 14);
        float* __restrict__ o1 = out + ((size_t)g1 << 14);
#pragma unroll
        for (int u = 0; u < 2; u++) {
            const int cl = wc * 32 + u * 16 + q * 4;
            const int gc = b0 + cl;
            const float4 sj = *(const float4*)&sqb[cl];
            const float* p0 = acc[mt][2 * u];
            const float* p1 = acc[mt][2 * u + 1];
            float4 w0, w1;
            w0.x = dist_val(si0, sj.x, p0[0]);
            w0.y = dist_val(si0, sj.y, p0[1]);
            w0.z = dist_val(si0, sj.z, p1[0]);
            w0.w = dist_val(si0, sj.w, p1[1]);
            w1.x = dist_val(si1, sj.x, p0[2]);
            w1.y = dist_val(si1, sj.y, p0[3]);
            w1.z = dist_val(si1, sj.z, p1[2]);
            w1.w = dist_val(si1, sj.w, p1[3]);
            if (diag) {
                const int d0 = g0 - gc;
                if (d0 >= 0 && d0 < 4) ((float*)&w0)[d0] = 0.0f;
                const int d1 = g1 - gc;
                if (d1 >= 0 && d1 < 4) ((float*)&w1)[d1] = 0.0f;
            }
            *(float4*)(o0 + gc) = w0;
            *(float4*)(o1 + gc) = w1;
        }
    }
}

extern "C" void kernel_launch(void* const* d_in, const int* in_sizes, int n_in,
                              void* d_out, int out_size)
{
    (void)in_sizes; (void)n_in; (void)out_size;
    const float* x = (const float*)d_in[0];
    float* out = (float*)d_out;
    prep_kernel<<<NPTS / 256, 256>>>(x);
    dim3 grid(NPTS / 128, NPTS / 128);
    cdist_mma_kernel<<<grid, 256>>>(out);
}